// round 2
// baseline (speedup 1.0000x reference)
#include <cuda_runtime.h>
#include <cstdint>

#define N_EMB   8192
#define DDIM    256
#define BB      32
#define HH      32
#define WW      32
#define HW      1024            // H*W
#define NQ      32768           // B*H*W
#define ZQ_ELEMS 8388608        // B*D*H*W
#define NSPLIT  4
#define KSPLIT  (N_EMB / NSPLIT)   // 2048
#define QT      128             // queries per CTA
#define ET      128             // embedding tile
#define DK      16              // d-chunk
#define ES_STRIDE 132           // padded Es row (floats)

// dynamic smem layout (floats): Zs[256][128] | Es[16][132] | Rv[128][16] | Ri[128][16]
#define SM_ZS    0
#define SM_ES    (DDIM * QT)                    // 32768
#define SM_RV    (SM_ES + DK * ES_STRIDE)       // 34880
#define SM_RI    (SM_RV + QT * 16)              // 36928
#define SM_FLOATS (SM_RI + QT * 16)             // 38976
#define SMEM_BYTES (SM_FLOATS * 4)              // 155904

__device__ float  g_ehn[N_EMB];
__device__ float  g_pval[NSPLIT * NQ];
__device__ int    g_pidx[NSPLIT * NQ];
__device__ int    g_idx[NQ];
__device__ double g_diff;

__device__ __forceinline__ unsigned long long pack2(float x) {
    unsigned long long r;
    asm("mov.b64 %0, {%1, %1};" : "=l"(r) : "r"(__float_as_uint(x)));
    return r;
}
#define FFMA2(acc, a, b) \
    asm("fma.rn.f32x2 %0, %1, %2, %0;" : "+l"(acc) : "l"(a), "l"(b))

// ---------------------------------------------------------------------------
// k_prep: 0.5*||e_k||^2 for all codes; zero the diff accumulator.
// grid 1024, block 256 (one warp per embedding row, 8 rows/block)
// ---------------------------------------------------------------------------
__global__ void k_prep(const float* __restrict__ emb) {
    if (blockIdx.x == 0 && threadIdx.x == 0) g_diff = 0.0;
    int row  = blockIdx.x * 8 + (threadIdx.x >> 5);
    int lane = threadIdx.x & 31;
    const float4* e4 = (const float4*)(emb + (size_t)row * DDIM);
    float s = 0.f;
    for (int i = lane; i < DDIM / 4; i += 32) {
        float4 v = e4[i];
        s += v.x * v.x + v.y * v.y + v.z * v.z + v.w * v.w;
    }
#pragma unroll
    for (int o = 16; o; o >>= 1) s += __shfl_xor_sync(0xffffffffu, s, o);
    if (lane == 0) g_ehn[row] = 0.5f * s;
}

// ---------------------------------------------------------------------------
// k_argmin: tiled score GEMM + running argmin.
// grid (NQ/QT, NSPLIT), block 256 (16x16 layout, 8q x 8e per thread)
// score_k = 0.5||e_k||^2 - z.e_k   (argmin == reference argmin)
// ---------------------------------------------------------------------------
__global__ void __launch_bounds__(256, 1)
k_argmin(const float* __restrict__ z, const float* __restrict__ emb) {
    extern __shared__ float sm[];
    float* Zs = sm + SM_ZS;
    float* Es = sm + SM_ES;
    float* Rv = sm + SM_RV;
    int*   Ri = (int*)(sm + SM_RI);

    const int tid = threadIdx.x;
    const int tx  = tid & 15;     // embedding cols
    const int ty  = tid >> 4;     // query rows
    const int qt  = blockIdx.x;
    const int sp  = blockIdx.y;
    const int qbase = qt * QT;
    const int b  = qbase / HW;
    const int nb = qbase % HW;
    const float* zb = z + (size_t)b * DDIM * HW + nb;

    // Stage the full 128x256 query tile: Zs[d][q] (q contiguous -> coalesced)
    {
        const int q0 = (tid & 31) * 4;
        for (int d = tid >> 5; d < DDIM; d += 8) {
            float4 v = *(const float4*)(zb + (size_t)d * HW + q0);
            *(float4*)(Zs + d * QT + q0) = v;
        }
    }
    __syncthreads();

    float bv[8];
    int   bi[8];
#pragma unroll
    for (int i = 0; i < 8; i++) { bv[i] = 3.4e38f; bi[i] = 0; }

    const int kbase = sp * KSPLIT;
    for (int et = 0; et < KSPLIT; et += ET) {
        const int e0 = kbase + et;

        unsigned long long acc[8][4];
#pragma unroll
        for (int i = 0; i < 8; i++)
#pragma unroll
            for (int jp = 0; jp < 4; jp++) acc[i][jp] = 0ull;

        float ehnv[8];
#pragma unroll
        for (int j = 0; j < 8; j++) ehnv[j] = g_ehn[e0 + tx * 8 + j];

        for (int dc = 0; dc < DDIM; dc += DK) {
            // Es[kk][e] = emb[e0+e][dc+kk], kk<16
            {
                const int e  = tid >> 1;
                const int k8 = (tid & 1) * 8;
                const float* src = emb + (size_t)(e0 + e) * DDIM + dc + k8;
                float4 a0 = *(const float4*)(src);
                float4 a1 = *(const float4*)(src + 4);
                Es[(k8 + 0) * ES_STRIDE + e] = a0.x;
                Es[(k8 + 1) * ES_STRIDE + e] = a0.y;
                Es[(k8 + 2) * ES_STRIDE + e] = a0.z;
                Es[(k8 + 3) * ES_STRIDE + e] = a0.w;
                Es[(k8 + 4) * ES_STRIDE + e] = a1.x;
                Es[(k8 + 5) * ES_STRIDE + e] = a1.y;
                Es[(k8 + 6) * ES_STRIDE + e] = a1.z;
                Es[(k8 + 7) * ES_STRIDE + e] = a1.w;
            }
            __syncthreads();
#pragma unroll
            for (int kk = 0; kk < DK; kk++) {
                const float* zr = Zs + (dc + kk) * QT + ty * 8;
                float4 z0 = *(const float4*)zr;
                float4 z1 = *(const float4*)(zr + 4);
                unsigned long long zz[8];
                zz[0] = pack2(z0.x); zz[1] = pack2(z0.y);
                zz[2] = pack2(z0.z); zz[3] = pack2(z0.w);
                zz[4] = pack2(z1.x); zz[5] = pack2(z1.y);
                zz[6] = pack2(z1.z); zz[7] = pack2(z1.w);
                const ulonglong2* er =
                    (const ulonglong2*)(Es + kk * ES_STRIDE + tx * 8);
                ulonglong2 ea = er[0], eb = er[1];
                unsigned long long ee[4] = {ea.x, ea.y, eb.x, eb.y};
#pragma unroll
                for (int i = 0; i < 8; i++) {
                    FFMA2(acc[i][0], zz[i], ee[0]);
                    FFMA2(acc[i][1], zz[i], ee[1]);
                    FFMA2(acc[i][2], zz[i], ee[2]);
                    FFMA2(acc[i][3], zz[i], ee[3]);
                }
            }
            __syncthreads();
        }

        // epilogue: score = 0.5||e||^2 - dot; running argmin (ascending e ->
        // strict '<' keeps the lowest index on ties, matching argmin order)
#pragma unroll
        for (int i = 0; i < 8; i++) {
#pragma unroll
            for (int jp = 0; jp < 4; jp++) {
                float lo = __uint_as_float((unsigned)(acc[i][jp] & 0xffffffffull));
                float hi = __uint_as_float((unsigned)(acc[i][jp] >> 32));
                int j0 = 2 * jp;
                float v0 = ehnv[j0] - lo;
                if (v0 < bv[i]) { bv[i] = v0; bi[i] = e0 + tx * 8 + j0; }
                float v1 = ehnv[j0 + 1] - hi;
                if (v1 < bv[i]) { bv[i] = v1; bi[i] = e0 + tx * 8 + j0 + 1; }
            }
        }
    }

    // cross-tx reduction (tx ascending == e ascending within a tile)
#pragma unroll
    for (int i = 0; i < 8; i++) {
        int q = ty * 8 + i;
        Rv[q * 16 + tx] = bv[i];
        Ri[q * 16 + tx] = bi[i];
    }
    __syncthreads();
    if (tid < QT) {
        float best = Rv[tid * 16];
        int   bidx = Ri[tid * 16];
#pragma unroll
        for (int t = 1; t < 16; t++) {
            float v = Rv[tid * 16 + t];
            if (v < best) { best = v; bidx = Ri[tid * 16 + t]; }
        }
        g_pval[sp * NQ + qbase + tid] = best;
        g_pidx[sp * NQ + qbase + tid] = bidx;
    }
}

// ---------------------------------------------------------------------------
// k_reduce: merge split-K partials (ascending split == ascending k)
// ---------------------------------------------------------------------------
__global__ void k_reduce(float* __restrict__ out) {
    int n = blockIdx.x * 256 + threadIdx.x;
    float best = g_pval[n];
    int   bidx = g_pidx[n];
#pragma unroll
    for (int s = 1; s < NSPLIT; s++) {
        float v = g_pval[s * NQ + n];
        if (v < best) { best = v; bidx = g_pidx[s * NQ + n]; }
    }
    g_idx[n] = bidx;
    out[ZQ_ELEMS + 1 + n] = (float)bidx;
}

// ---------------------------------------------------------------------------
// k_scatter: z_q[b][c][h][w] = emb[idx[n]][c] via smem transpose; diff partials
// grid 1024 (= b*32 + h), block 256
// ---------------------------------------------------------------------------
__global__ void k_scatter(const float* __restrict__ z,
                          const float* __restrict__ emb,
                          float* __restrict__ out) {
    __shared__ float Ts[32][257];
    __shared__ int   sidx[32];
    __shared__ float spart[8];
    const int bh = blockIdx.x;
    const int b  = bh >> 5;
    const int h  = bh & 31;
    const int t  = threadIdx.x;

    if (t < 32) sidx[t] = g_idx[b * HW + h * 32 + t];
    __syncthreads();
    {
        const int wr = t >> 3;
        const int c0 = (t & 7) * 32;
        const float* er = emb + (size_t)sidx[wr] * DDIM + c0;
        for (int c = 0; c < 32; c += 4) {
            float4 v = *(const float4*)(er + c);
            Ts[wr][c0 + c + 0] = v.x;
            Ts[wr][c0 + c + 1] = v.y;
            Ts[wr][c0 + c + 2] = v.z;
            Ts[wr][c0 + c + 3] = v.w;
        }
    }
    __syncthreads();

    float ds = 0.f;
    const int w  = t & 31;
    const int cg = t >> 5;
    const size_t basebh = (size_t)b * DDIM * HW + (size_t)h * 32;
    for (int c = cg; c < DDIM; c += 8) {
        float v = Ts[w][c];
        size_t g = basebh + (size_t)c * HW + w;
        float zv = z[g];
        out[g] = v;
        float df = v - zv;
        ds += df * df;
    }
#pragma unroll
    for (int o = 16; o; o >>= 1) ds += __shfl_xor_sync(0xffffffffu, ds, o);
    if ((t & 31) == 0) spart[t >> 5] = ds;
    __syncthreads();
    if (t == 0) {
        float s = 0.f;
#pragma unroll
        for (int i = 0; i < 8; i++) s += spart[i];
        atomicAdd(&g_diff, (double)s);
    }
}

__global__ void k_final(float* __restrict__ out) {
    out[ZQ_ELEMS] = (float)(0.25 * g_diff / (double)ZQ_ELEMS);
}

// ---------------------------------------------------------------------------
extern "C" void kernel_launch(void* const* d_in, const int* in_sizes, int n_in,
                              void* d_out, int out_size) {
    const float* z   = (const float*)d_in[0];
    const float* emb = (const float*)d_in[1];
    float* out = (float*)d_out;

    cudaFuncSetAttribute(k_argmin,
                         cudaFuncAttributeMaxDynamicSharedMemorySize,
                         SMEM_BYTES);

    k_prep<<<N_EMB / 8, 256>>>(emb);
    dim3 g(NQ / QT, NSPLIT);
    k_argmin<<<g, 256, SMEM_BYTES>>>(z, emb);
    k_reduce<<<NQ / 256, 256>>>(out);
    k_scatter<<<BB * HH, 256>>>(z, emb, out);
    k_final<<<1, 1>>>(out);
}

// round 5
// speedup vs baseline: 2.4482x; 2.4482x over previous
#include <cuda_runtime.h>
#include <cstdint>
#include <cfloat>

#define N_EMB   8192
#define DDIM    256
#define BB      32
#define HW      1024
#define NQ      32768
#define ZQ_ELEMS 8388608
#define SPLITS  4
#define KSPL    2048
#define QT      128
#define CCH     128            // codes per chunk
#define GCH     256            // 32-code slices total
#define TAU     0.35f
#define BPAD    68             // padded B row (floats) per 64-k stage

#define SM_A    0              // A frags: 32768 u32 = 131072 B
#define SM_B    131072         // 2 stages x 34816 B
#define SM_EH   200704         // 2048 floats = 8192 B
#define SM_RED  208896         // rv1/ri1/rv2: 3 x 2048 B
#define SMEM_ALLOC 215040

__device__ float  g_ehn[N_EMB];
__device__ float  g_p1v[SPLITS * NQ];
__device__ int    g_p1i[SPLITS * NQ];
__device__ float  g_p2v[SPLITS * NQ];
__device__ float  g_cmin[GCH * NQ];
__device__ float  g_b1[NQ];
__device__ int    g_idx[NQ];
__device__ int    g_flag[NQ];
__device__ int    g_nflag;
__device__ double g_diff;

__device__ __forceinline__ uint32_t smem_u32(const void* p) {
    uint32_t a;
    asm("{ .reg .u64 t; cvta.to.shared.u64 t, %1; cvt.u32.u64 %0, t; }"
        : "=r"(a) : "l"(p));
    return a;
}
__device__ __forceinline__ uint32_t f2tf32(float x) {
    uint32_t r;
    asm("cvt.rna.tf32.f32 %0, %1;" : "=r"(r) : "f"(x));
    return r;
}
__device__ __forceinline__ void cp16(uint32_t s, const void* g) {
    asm volatile("cp.async.cg.shared.global [%0], [%1], 16;"
                 :: "r"(s), "l"(g) : "memory");
}
#define CP_COMMIT() asm volatile("cp.async.commit_group;" ::: "memory")
#define CP_WAIT1()  asm volatile("cp.async.wait_group 1;" ::: "memory")

#define MMA_TF32(d, a, b0, b1) \
    asm volatile("mma.sync.aligned.m16n8k8.row.col.f32.tf32.tf32.f32 " \
        "{%0,%1,%2,%3},{%4,%5,%6,%7},{%8,%9},{%0,%1,%2,%3};" \
        : "+f"((d)[0]), "+f"((d)[1]), "+f"((d)[2]), "+f"((d)[3]) \
        : "r"((a).x), "r"((a).y), "r"((a).z), "r"((a).w), "r"(b0), "r"(b1))

__global__ void k_prep(const float* __restrict__ emb) {
    if (blockIdx.x == 0 && threadIdx.x == 0) { g_diff = 0.0; g_nflag = 0; }
    int row  = blockIdx.x * 8 + (threadIdx.x >> 5);
    int lane = threadIdx.x & 31;
    const float4* e4 = (const float4*)(emb + (size_t)row * DDIM);
    float s = 0.f;
    for (int i = lane; i < DDIM / 4; i += 32) {
        float4 v = e4[i];
        s += v.x * v.x + v.y * v.y + v.z * v.z + v.w * v.w;
    }
#pragma unroll
    for (int o = 16; o; o >>= 1) s += __shfl_xor_sync(0xffffffffu, s, o);
    if (lane == 0) g_ehn[row] = 0.5f * s;
}

// grid (NQ/QT=256, SPLITS=4), block 256 (8 warps: 2M x 4N)
__global__ void __launch_bounds__(256, 1)
k_gemm(const float* __restrict__ z, const float* __restrict__ emb) {
    extern __shared__ char sm[];
    uint32_t* Af  = (uint32_t*)(sm + SM_A);
    float*    ehs = (float*)(sm + SM_EH);
    float*    rv1 = (float*)(sm + SM_RED);
    int*      ri1 = (int*)(sm + SM_RED + 2048);
    float*    rv2 = (float*)(sm + SM_RED + 4096);
    const uint32_t smB = smem_u32(sm) + SM_B;

    const int tid = threadIdx.x, wid = tid >> 5, lane = tid & 31;
    const int warpM = wid >> 2, warpN = wid & 3;
    const int g = lane >> 2, t = lane & 3;
    const int qbase = blockIdx.x * QT, sp = blockIdx.y;
    const int bb = qbase / HW, nb = qbase % HW;
    const int kbase = sp * KSPL;

    for (int i = tid; i < KSPL; i += 256) ehs[i] = g_ehn[kbase + i];

    // A staging: z[128 q][256 k] -> tf32 fragment layout [ks][mtile][lane][4]
    const float* zb = z + (size_t)bb * DDIM * HW + nb;
    for (int i = tid; i < QT * DDIM; i += 256) {
        int row = i & 127, k = i >> 7;
        uint32_t tv = f2tf32(zb[(size_t)k * HW + row]);
        int mt = row >> 4, rr = row & 15;
        int gg = rr & 7, reg = (rr >> 3) | (((k & 7) >= 4) ? 2 : 0);
        int ln = gg * 4 + (k & 3), ks = k >> 3;
        Af[((ks * 8 + mt) * 32 + ln) * 4 + reg] = tv;
    }
    __syncthreads();

    auto prefetch = [&](int s) {
        int cc = s >> 2, kb = s & 3, buf = s & 1;
        const float* src = emb + (size_t)(kbase + cc * CCH) * DDIM + kb * 64;
        uint32_t dst = smB + buf * 34816;
#pragma unroll
        for (int j = 0; j < 8; j++) {
            int idx = j * 256 + tid, code = idx >> 4, kq = idx & 15;
            cp16(dst + code * (BPAD * 4) + kq * 16,
                 src + (size_t)code * DDIM + kq * 4);
        }
    };

    float D[4][4][4];
    float bv1[4][2], bv2[4][2];
    int   bix[4][2];
#pragma unroll
    for (int a = 0; a < 4; a++)
#pragma unroll
        for (int h = 0; h < 2; h++) {
            bv1[a][h] = FLT_MAX; bv2[a][h] = FLT_MAX; bix[a][h] = 0;
        }

    prefetch(0);
    CP_COMMIT();
    for (int s = 0; s < 64; s++) {
        if (s < 63) prefetch(s + 1);
        CP_COMMIT();
        CP_WAIT1();
        __syncthreads();
        if ((s & 3) == 0) {
#pragma unroll
            for (int mt = 0; mt < 4; mt++)
#pragma unroll
                for (int nt = 0; nt < 4; nt++)
#pragma unroll
                    for (int c = 0; c < 4; c++) D[mt][nt][c] = 0.f;
        }
        const float* Bbuf = (const float*)(sm + SM_B + (s & 1) * 34816);
#pragma unroll
        for (int ks = 0; ks < 8; ks++) {
            int ksg = (s & 3) * 8 + ks;
            uint4 a[4];
#pragma unroll
            for (int mt = 0; mt < 4; mt++)
                a[mt] = *(const uint4*)(Af + ((ksg * 8 + warpM * 4 + mt) * 32 + lane) * 4);
#pragma unroll
            for (int nt = 0; nt < 4; nt++) {
                int code = warpN * 32 + nt * 8 + g;
                uint32_t b0 = __float_as_uint(Bbuf[code * BPAD + ks * 8 + t]);
                uint32_t b1 = __float_as_uint(Bbuf[code * BPAD + ks * 8 + t + 4]);
#pragma unroll
                for (int mt = 0; mt < 4; mt++)
                    MMA_TF32(D[mt][nt], a[mt], b0, b1);
            }
        }
        if ((s & 3) == 3) {
            const int cc = s >> 2;
            float eh[4][2];
#pragma unroll
            for (int nt = 0; nt < 4; nt++) {
                int cl = cc * CCH + warpN * 32 + nt * 8 + 2 * t;
                eh[nt][0] = ehs[cl]; eh[nt][1] = ehs[cl + 1];
            }
#pragma unroll
            for (int mt = 0; mt < 4; mt++)
#pragma unroll
                for (int h = 0; h < 2; h++) {
                    float cm = FLT_MAX;
#pragma unroll
                    for (int nt = 0; nt < 4; nt++)
#pragma unroll
                        for (int c = 0; c < 2; c++) {
                            float v = eh[nt][c] - D[mt][nt][h * 2 + c];
                            int gi = kbase + cc * CCH + warpN * 32 + nt * 8 + 2 * t + c;
                            cm = fminf(cm, v);
                            if (v < bv1[mt][h] ||
                                (v == bv1[mt][h] && gi < bix[mt][h])) {
                                bv2[mt][h] = bv1[mt][h];
                                bv1[mt][h] = v; bix[mt][h] = gi;
                            } else {
                                bv2[mt][h] = fminf(bv2[mt][h], v);
                            }
                        }
                    cm = fminf(cm, __shfl_xor_sync(0xffffffffu, cm, 1));
                    cm = fminf(cm, __shfl_xor_sync(0xffffffffu, cm, 2));
                    if (t == 0) {
                        int slice = sp * 64 + cc * 4 + warpN;
                        int row = warpM * 64 + mt * 16 + h * 8 + g;
                        g_cmin[(size_t)slice * NQ + qbase + row] = cm;
                    }
                }
        }
        __syncthreads();
    }

    // merge across the 4 t-lanes, then across warpN via smem
#pragma unroll
    for (int mt = 0; mt < 4; mt++)
#pragma unroll
        for (int h = 0; h < 2; h++) {
            float v1 = bv1[mt][h], v2 = bv2[mt][h];
            int i1 = bix[mt][h];
#pragma unroll
            for (int o = 1; o <= 2; o <<= 1) {
                float pv1 = __shfl_xor_sync(0xffffffffu, v1, o);
                float pv2 = __shfl_xor_sync(0xffffffffu, v2, o);
                int   pi1 = __shfl_xor_sync(0xffffffffu, i1, o);
                if (pv1 < v1 || (pv1 == v1 && pi1 < i1)) {
                    v2 = fminf(v1, pv2); v1 = pv1; i1 = pi1;
                } else {
                    v2 = fminf(pv1, v2);
                }
            }
            if (t == 0) {
                int row = warpM * 64 + mt * 16 + h * 8 + g;
                rv1[row * 4 + warpN] = v1;
                ri1[row * 4 + warpN] = i1;
                rv2[row * 4 + warpN] = v2;
            }
        }
    __syncthreads();
    if (tid < 128) {
        float v1 = rv1[tid * 4]; int i1 = ri1[tid * 4]; float v2 = rv2[tid * 4];
#pragma unroll
        for (int wn = 1; wn < 4; wn++) {
            float pv1 = rv1[tid * 4 + wn], pv2 = rv2[tid * 4 + wn];
            int   pi1 = ri1[tid * 4 + wn];
            if (pv1 < v1 || (pv1 == v1 && pi1 < i1)) {
                v2 = fminf(v1, pv2); v1 = pv1; i1 = pi1;
            } else {
                v2 = fminf(pv1, v2);
            }
        }
        g_p1v[sp * NQ + qbase + tid] = v1;
        g_p1i[sp * NQ + qbase + tid] = i1;
        g_p2v[sp * NQ + qbase + tid] = v2;
    }
}

__global__ void k_reduce() {
    int q = blockIdx.x * 256 + threadIdx.x;
    float b1 = FLT_MAX, b2 = FLT_MAX;
    int i1 = 0;
#pragma unroll
    for (int s = 0; s < SPLITS; s++) {
        float v1 = g_p1v[s * NQ + q];
        int   ii = g_p1i[s * NQ + q];
        float v2 = g_p2v[s * NQ + q];
        if (v1 < b1) { b2 = b1; b1 = v1; i1 = ii; }
        else if (v1 < b2) b2 = v1;
        if (v2 < b2) b2 = v2;
    }
    g_idx[q] = i1;
    g_b1[q]  = b1;
    if (b2 - b1 <= TAU) {
        int p = atomicAdd(&g_nflag, 1);
        g_flag[p] = q;
    }
}

__global__ void __launch_bounds__(256, 4)
k_refine(const float* __restrict__ z, const float* __restrict__ emb) {
    __shared__ float zrow[DDIM];
    __shared__ float wbv[8];
    __shared__ int   wbi[8];
    const int tid = threadIdx.x, wid = tid >> 5, lane = tid & 31;
    const int nf = g_nflag;
    for (int fi = blockIdx.x; fi < nf; fi += gridDim.x) {
        const int q = g_flag[fi];
        __syncthreads();
        zrow[tid] = z[((size_t)(q >> 10) * DDIM + tid) * HW + (q & (HW - 1))];
        __syncthreads();
        const float thr = g_b1[q] + TAU;
        float bv = FLT_MAX;
        int   bi = 0x7fffffff;
        const float* zr = zrow + lane * 8;
        float z0 = zr[0], z1 = zr[1], z2 = zr[2], z3 = zr[3];
        float z4 = zr[4], z5 = zr[5], z6 = zr[6], z7 = zr[7];
        for (int gc = 0; gc < GCH; gc++) {
            if (g_cmin[(size_t)gc * NQ + q] > thr) continue;
            const int cb = gc * 32 + wid * 4;
            for (int cc = 0; cc < 4; cc++) {
                const int code = cb + cc;
                const float* er = emb + (size_t)code * DDIM + lane * 8;
                float4 a = *(const float4*)er;
                float4 bq = *(const float4*)(er + 4);
                float s = a.x * z0 + a.y * z1 + a.z * z2 + a.w * z3
                        + bq.x * z4 + bq.y * z5 + bq.z * z6 + bq.w * z7;
#pragma unroll
                for (int o = 16; o; o >>= 1)
                    s += __shfl_xor_sync(0xffffffffu, s, o);
                float v = g_ehn[code] - s;
                if (v < bv || (v == bv && code < bi)) { bv = v; bi = code; }
            }
        }
        if (lane == 0) { wbv[wid] = bv; wbi[wid] = bi; }
        __syncthreads();
        if (tid == 0) {
            float fv = wbv[0]; int fx = wbi[0];
#pragma unroll
            for (int w2 = 1; w2 < 8; w2++)
                if (wbv[w2] < fv || (wbv[w2] == fv && wbi[w2] < fx)) {
                    fv = wbv[w2]; fx = wbi[w2];
                }
            g_idx[q] = fx;
        }
        __syncthreads();
    }
}

__global__ void k_scatter(const float* __restrict__ z,
                          const float* __restrict__ emb,
                          float* __restrict__ out) {
    __shared__ float Ts[32][257];
    __shared__ int   sidx[32];
    __shared__ float spart[8];
    const int bh = blockIdx.x;
    const int b  = bh >> 5;
    const int h  = bh & 31;
    const int t  = threadIdx.x;

    if (t < 32) {
        int ix = g_idx[b * HW + h * 32 + t];
        sidx[t] = ix;
        out[ZQ_ELEMS + 1 + b * HW + h * 32 + t] = (float)ix;
    }
    __syncthreads();
    {
        const int wr = t >> 3;
        const int c0 = (t & 7) * 32;
        const float* er = emb + (size_t)sidx[wr] * DDIM + c0;
        for (int c = 0; c < 32; c += 4) {
            float4 v = *(const float4*)(er + c);
            Ts[wr][c0 + c + 0] = v.x;
            Ts[wr][c0 + c + 1] = v.y;
            Ts[wr][c0 + c + 2] = v.z;
            Ts[wr][c0 + c + 3] = v.w;
        }
    }
    __syncthreads();

    float ds = 0.f;
    const int w  = t & 31;
    const int cg = t >> 5;
    const size_t basebh = (size_t)b * DDIM * HW + (size_t)h * 32;
    for (int c = cg; c < DDIM; c += 8) {
        float v = Ts[w][c];
        size_t gg = basebh + (size_t)c * HW + w;
        float zv = z[gg];
        out[gg] = v;
        float df = v - zv;
        ds += df * df;
    }
#pragma unroll
    for (int o = 16; o; o >>= 1) ds += __shfl_xor_sync(0xffffffffu, ds, o);
    if ((t & 31) == 0) spart[t >> 5] = ds;
    __syncthreads();
    if (t == 0) {
        float s = 0.f;
#pragma unroll
        for (int i = 0; i < 8; i++) s += spart[i];
        atomicAdd(&g_diff, (double)s);
    }
}

__global__ void k_final(float* __restrict__ out) {
    out[ZQ_ELEMS] = (float)(0.25 * g_diff / (double)ZQ_ELEMS);
}

extern "C" void kernel_launch(void* const* d_in, const int* in_sizes, int n_in,
                              void* d_out, int out_size) {
    const float* z   = (const float*)d_in[0];
    const float* emb = (const float*)d_in[1];
    float* out = (float*)d_out;

    cudaFuncSetAttribute(k_gemm,
                         cudaFuncAttributeMaxDynamicSharedMemorySize,
                         SMEM_ALLOC);

    k_prep<<<N_EMB / 8, 256>>>(emb);
    dim3 g(NQ / QT, SPLITS);
    k_gemm<<<g, 256, SMEM_ALLOC>>>(z, emb);
    k_reduce<<<NQ / 256, 256>>>();
    k_refine<<<2048, 256>>>(z, emb);
    k_scatter<<<BB * (HW / 32), 256>>>(z, emb, out);
    k_final<<<1, 1>>>(out);
}

// round 6
// speedup vs baseline: 3.2589x; 1.3312x over previous
#include <cuda_runtime.h>
#include <cstdint>
#include <cfloat>

#define N_EMB   8192
#define DDIM    256
#define BB      32
#define HW      1024
#define NQ      32768
#define ZQ_ELEMS 8388608
#define SPLITS  4
#define KSPL    2048
#define QT      128
#define CCH     128            // codes per chunk
#define GCH     256            // 32-code slices total
#define TAU     0.12f
#define BPAD    68             // padded B row (floats) per 64-k stage

#define SM_A    0              // A frags: 32768 u32 = 131072 B
#define SM_B    131072         // 2 stages x 34816 B
#define SM_EH   200704         // 2048 floats = 8192 B
#define SM_RED  208896         // rv1/ri1/rv2: 3 x 2048 B
#define SMEM_ALLOC 215040

__device__ float  g_ehn[N_EMB];
__device__ float  g_p1v[SPLITS * NQ];
__device__ int    g_p1i[SPLITS * NQ];
__device__ float  g_p2v[SPLITS * NQ];
__device__ float  g_cmin[GCH * NQ];
__device__ float  g_b1[NQ];
__device__ int    g_idx[NQ];
__device__ int    g_flag[NQ];
__device__ int    g_nflag;
__device__ double g_diff;

__device__ __forceinline__ uint32_t smem_u32(const void* p) {
    uint32_t a;
    asm("{ .reg .u64 t; cvta.to.shared.u64 t, %1; cvt.u32.u64 %0, t; }"
        : "=r"(a) : "l"(p));
    return a;
}
__device__ __forceinline__ uint32_t f2tf32(float x) {
    uint32_t r;
    asm("cvt.rna.tf32.f32 %0, %1;" : "=r"(r) : "f"(x));
    return r;
}
__device__ __forceinline__ void cp16(uint32_t s, const void* g) {
    asm volatile("cp.async.cg.shared.global [%0], [%1], 16;"
                 :: "r"(s), "l"(g) : "memory");
}
#define CP_COMMIT() asm volatile("cp.async.commit_group;" ::: "memory")
#define CP_WAIT1()  asm volatile("cp.async.wait_group 1;" ::: "memory")

#define MMA_TF32(d, a, b0, b1) \
    asm volatile("mma.sync.aligned.m16n8k8.row.col.f32.tf32.tf32.f32 " \
        "{%0,%1,%2,%3},{%4,%5,%6,%7},{%8,%9},{%0,%1,%2,%3};" \
        : "+f"((d)[0]), "+f"((d)[1]), "+f"((d)[2]), "+f"((d)[3]) \
        : "r"((a).x), "r"((a).y), "r"((a).z), "r"((a).w), "r"(b0), "r"(b1))

__global__ void k_prep(const float* __restrict__ emb) {
    if (blockIdx.x == 0 && threadIdx.x == 0) { g_diff = 0.0; g_nflag = 0; }
    int row  = blockIdx.x * 8 + (threadIdx.x >> 5);
    int lane = threadIdx.x & 31;
    const float4* e4 = (const float4*)(emb + (size_t)row * DDIM);
    float s = 0.f;
    for (int i = lane; i < DDIM / 4; i += 32) {
        float4 v = e4[i];
        s += v.x * v.x + v.y * v.y + v.z * v.z + v.w * v.w;
    }
#pragma unroll
    for (int o = 16; o; o >>= 1) s += __shfl_xor_sync(0xffffffffu, s, o);
    if (lane == 0) g_ehn[row] = 0.5f * s;
}

// grid (NQ/QT=256, SPLITS=4), block 256 (8 warps: 2M x 4N)
__global__ void __launch_bounds__(256, 1)
k_gemm(const float* __restrict__ z, const float* __restrict__ emb) {
    extern __shared__ char sm[];
    uint32_t* Af  = (uint32_t*)(sm + SM_A);
    float*    ehs = (float*)(sm + SM_EH);
    float*    rv1 = (float*)(sm + SM_RED);
    int*      ri1 = (int*)(sm + SM_RED + 2048);
    float*    rv2 = (float*)(sm + SM_RED + 4096);
    const uint32_t smB = smem_u32(sm) + SM_B;

    const int tid = threadIdx.x, wid = tid >> 5, lane = tid & 31;
    const int warpM = wid >> 2, warpN = wid & 3;
    const int g = lane >> 2, t = lane & 3;
    const int qbase = blockIdx.x * QT, sp = blockIdx.y;
    const int bb = qbase / HW, nb = qbase % HW;
    const int kbase = sp * KSPL;

    for (int i = tid; i < KSPL; i += 256) ehs[i] = g_ehn[kbase + i];

    // A staging: z[128 q][256 k] -> tf32 fragment layout [ks][mtile][lane][4]
    const float* zb = z + (size_t)bb * DDIM * HW + nb;
    for (int i = tid; i < QT * DDIM; i += 256) {
        int row = i & 127, k = i >> 7;
        uint32_t tv = f2tf32(zb[(size_t)k * HW + row]);
        int mt = row >> 4, rr = row & 15;
        int gg = rr & 7, reg = (rr >> 3) | (((k & 7) >= 4) ? 2 : 0);
        int ln = gg * 4 + (k & 3), ks = k >> 3;
        Af[((ks * 8 + mt) * 32 + ln) * 4 + reg] = tv;
    }
    __syncthreads();

    auto prefetch = [&](int s) {
        int cc = s >> 2, kb = s & 3, buf = s & 1;
        const float* src = emb + (size_t)(kbase + cc * CCH) * DDIM + kb * 64;
        uint32_t dst = smB + buf * 34816;
#pragma unroll
        for (int j = 0; j < 8; j++) {
            int idx = j * 256 + tid, code = idx >> 4, kq = idx & 15;
            cp16(dst + code * (BPAD * 4) + kq * 16,
                 src + (size_t)code * DDIM + kq * 4);
        }
    };

    float D[4][4][4];
    float bv1[4][2], bv2[4][2];
    int   bix[4][2];
#pragma unroll
    for (int a = 0; a < 4; a++)
#pragma unroll
        for (int h = 0; h < 2; h++) {
            bv1[a][h] = FLT_MAX; bv2[a][h] = FLT_MAX; bix[a][h] = 0;
        }

    prefetch(0);
    CP_COMMIT();
    for (int s = 0; s < 64; s++) {
        if (s < 63) prefetch(s + 1);
        CP_COMMIT();
        CP_WAIT1();
        __syncthreads();
        if ((s & 3) == 0) {
#pragma unroll
            for (int mt = 0; mt < 4; mt++)
#pragma unroll
                for (int nt = 0; nt < 4; nt++)
#pragma unroll
                    for (int c = 0; c < 4; c++) D[mt][nt][c] = 0.f;
        }
        const float* Bbuf = (const float*)(sm + SM_B + (s & 1) * 34816);
#pragma unroll
        for (int ks = 0; ks < 8; ks++) {
            int ksg = (s & 3) * 8 + ks;
            uint4 a[4];
#pragma unroll
            for (int mt = 0; mt < 4; mt++)
                a[mt] = *(const uint4*)(Af + ((ksg * 8 + warpM * 4 + mt) * 32 + lane) * 4);
#pragma unroll
            for (int nt = 0; nt < 4; nt++) {
                int code = warpN * 32 + nt * 8 + g;
                uint32_t b0 = __float_as_uint(Bbuf[code * BPAD + ks * 8 + t]);
                uint32_t b1 = __float_as_uint(Bbuf[code * BPAD + ks * 8 + t + 4]);
#pragma unroll
                for (int mt = 0; mt < 4; mt++)
                    MMA_TF32(D[mt][nt], a[mt], b0, b1);
            }
        }
        if ((s & 3) == 3) {
            const int cc = s >> 2;
            float eh[4][2];
#pragma unroll
            for (int nt = 0; nt < 4; nt++) {
                int cl = cc * CCH + warpN * 32 + nt * 8 + 2 * t;
                eh[nt][0] = ehs[cl]; eh[nt][1] = ehs[cl + 1];
            }
#pragma unroll
            for (int mt = 0; mt < 4; mt++)
#pragma unroll
                for (int h = 0; h < 2; h++) {
                    float cm = FLT_MAX;
#pragma unroll
                    for (int nt = 0; nt < 4; nt++)
#pragma unroll
                        for (int c = 0; c < 2; c++) {
                            float v = eh[nt][c] - D[mt][nt][h * 2 + c];
                            int gi = kbase + cc * CCH + warpN * 32 + nt * 8 + 2 * t + c;
                            cm = fminf(cm, v);
                            if (v < bv1[mt][h] ||
                                (v == bv1[mt][h] && gi < bix[mt][h])) {
                                bv2[mt][h] = bv1[mt][h];
                                bv1[mt][h] = v; bix[mt][h] = gi;
                            } else {
                                bv2[mt][h] = fminf(bv2[mt][h], v);
                            }
                        }
                    cm = fminf(cm, __shfl_xor_sync(0xffffffffu, cm, 1));
                    cm = fminf(cm, __shfl_xor_sync(0xffffffffu, cm, 2));
                    if (t == 0) {
                        int slice = sp * 64 + cc * 4 + warpN;
                        int row = warpM * 64 + mt * 16 + h * 8 + g;
                        g_cmin[(size_t)slice * NQ + qbase + row] = cm;
                    }
                }
        }
        __syncthreads();
    }

    // merge across the 4 t-lanes, then across warpN via smem
#pragma unroll
    for (int mt = 0; mt < 4; mt++)
#pragma unroll
        for (int h = 0; h < 2; h++) {
            float v1 = bv1[mt][h], v2 = bv2[mt][h];
            int i1 = bix[mt][h];
#pragma unroll
            for (int o = 1; o <= 2; o <<= 1) {
                float pv1 = __shfl_xor_sync(0xffffffffu, v1, o);
                float pv2 = __shfl_xor_sync(0xffffffffu, v2, o);
                int   pi1 = __shfl_xor_sync(0xffffffffu, i1, o);
                if (pv1 < v1 || (pv1 == v1 && pi1 < i1)) {
                    v2 = fminf(v1, pv2); v1 = pv1; i1 = pi1;
                } else {
                    v2 = fminf(pv1, v2);
                }
            }
            if (t == 0) {
                int row = warpM * 64 + mt * 16 + h * 8 + g;
                rv1[row * 4 + warpN] = v1;
                ri1[row * 4 + warpN] = i1;
                rv2[row * 4 + warpN] = v2;
            }
        }
    __syncthreads();
    if (tid < 128) {
        float v1 = rv1[tid * 4]; int i1 = ri1[tid * 4]; float v2 = rv2[tid * 4];
#pragma unroll
        for (int wn = 1; wn < 4; wn++) {
            float pv1 = rv1[tid * 4 + wn], pv2 = rv2[tid * 4 + wn];
            int   pi1 = ri1[tid * 4 + wn];
            if (pv1 < v1 || (pv1 == v1 && pi1 < i1)) {
                v2 = fminf(v1, pv2); v1 = pv1; i1 = pi1;
            } else {
                v2 = fminf(pv1, v2);
            }
        }
        g_p1v[sp * NQ + qbase + tid] = v1;
        g_p1i[sp * NQ + qbase + tid] = i1;
        g_p2v[sp * NQ + qbase + tid] = v2;
    }
}

__global__ void k_reduce() {
    int q = blockIdx.x * 256 + threadIdx.x;
    float b1 = FLT_MAX, b2 = FLT_MAX;
    int i1 = 0;
#pragma unroll
    for (int s = 0; s < SPLITS; s++) {
        float v1 = g_p1v[s * NQ + q];
        int   ii = g_p1i[s * NQ + q];
        float v2 = g_p2v[s * NQ + q];
        if (v1 < b1) { b2 = b1; b1 = v1; i1 = ii; }
        else if (v1 < b2) b2 = v1;
        if (v2 < b2) b2 = v2;
    }
    g_idx[q] = i1;
    g_b1[q]  = b1;
    if (b2 - b1 <= TAU) {
        int p = atomicAdd(&g_nflag, 1);
        g_flag[p] = q;
    }
}

// block = 256 (8 warps). Per slice: 32 codes concurrently, code = wid*4 + grp,
// each 8-lane group computes one code's dot (32 dims/lane in registers).
__global__ void __launch_bounds__(256, 2)
k_refine(const float* __restrict__ z, const float* __restrict__ emb) {
    __shared__ float zs[DDIM];
    __shared__ short clist[GCH];
    __shared__ int   ncand;
    __shared__ float wv[8];
    __shared__ int   wi[8];
    const int tid = threadIdx.x, wid = tid >> 5, lane = tid & 31;
    const int grp = lane >> 3, gl = lane & 7;
    const int nf = g_nflag;
    for (int fi = blockIdx.x; fi < nf; fi += gridDim.x) {
        const int q = g_flag[fi];
        if (tid == 0) ncand = 0;
        __syncthreads();
        zs[tid] = z[((size_t)(q >> 10) * DDIM + tid) * HW + (q & (HW - 1))];
        __syncthreads();
        float4 zr[8];
#pragma unroll
        for (int j = 0; j < 8; j++) zr[j] = *(const float4*)(zs + gl * 32 + j * 4);
        const float thr = g_b1[q] + TAU;
        if (tid < GCH && g_cmin[(size_t)tid * NQ + q] <= thr) {
            int p = atomicAdd(&ncand, 1);
            clist[p] = (short)tid;
        }
        __syncthreads();
        const int nc = ncand;
        float bv = FLT_MAX;
        int   bi = 0x7fffffff;
        for (int ci = 0; ci < nc; ci++) {
            const int code = clist[ci] * 32 + wid * 4 + grp;
            const float4* er = (const float4*)(emb + (size_t)code * DDIM + gl * 32);
            float s = 0.f;
#pragma unroll
            for (int j = 0; j < 8; j++) {
                float4 e = er[j];
                s += e.x * zr[j].x + e.y * zr[j].y + e.z * zr[j].z + e.w * zr[j].w;
            }
            s += __shfl_xor_sync(0xffffffffu, s, 1);
            s += __shfl_xor_sync(0xffffffffu, s, 2);
            s += __shfl_xor_sync(0xffffffffu, s, 4);
            float v = g_ehn[code] - s;
            if (v < bv || (v == bv && code < bi)) { bv = v; bi = code; }
        }
#pragma unroll
        for (int o = 8; o <= 16; o <<= 1) {
            float pv = __shfl_xor_sync(0xffffffffu, bv, o);
            int   pi = __shfl_xor_sync(0xffffffffu, bi, o);
            if (pv < bv || (pv == bv && pi < bi)) { bv = pv; bi = pi; }
        }
        if (lane == 0) { wv[wid] = bv; wi[wid] = bi; }
        __syncthreads();
        if (tid == 0) {
            float fv = wv[0]; int fx = wi[0];
#pragma unroll
            for (int w2 = 1; w2 < 8; w2++)
                if (wv[w2] < fv || (wv[w2] == fv && wi[w2] < fx)) {
                    fv = wv[w2]; fx = wi[w2];
                }
            g_idx[q] = fx;
        }
        __syncthreads();
    }
}

__global__ void k_scatter(const float* __restrict__ z,
                          const float* __restrict__ emb,
                          float* __restrict__ out) {
    __shared__ float Ts[32][257];
    __shared__ int   sidx[32];
    __shared__ float spart[8];
    const int bh = blockIdx.x;
    const int b  = bh >> 5;
    const int h  = bh & 31;
    const int t  = threadIdx.x;

    if (t < 32) {
        int ix = g_idx[b * HW + h * 32 + t];
        sidx[t] = ix;
        out[ZQ_ELEMS + 1 + b * HW + h * 32 + t] = (float)ix;
    }
    __syncthreads();
    {
        const int wr = t >> 3;
        const int c0 = (t & 7) * 32;
        const float* er = emb + (size_t)sidx[wr] * DDIM + c0;
        for (int c = 0; c < 32; c += 4) {
            float4 v = *(const float4*)(er + c);
            Ts[wr][c0 + c + 0] = v.x;
            Ts[wr][c0 + c + 1] = v.y;
            Ts[wr][c0 + c + 2] = v.z;
            Ts[wr][c0 + c + 3] = v.w;
        }
    }
    __syncthreads();

    float ds = 0.f;
    const int w  = t & 31;
    const int cg = t >> 5;
    const size_t basebh = (size_t)b * DDIM * HW + (size_t)h * 32;
    for (int c = cg; c < DDIM; c += 8) {
        float v = Ts[w][c];
        size_t gg = basebh + (size_t)c * HW + w;
        float zv = z[gg];
        out[gg] = v;
        float df = v - zv;
        ds += df * df;
    }
#pragma unroll
    for (int o = 16; o; o >>= 1) ds += __shfl_xor_sync(0xffffffffu, ds, o);
    if ((t & 31) == 0) spart[t >> 5] = ds;
    __syncthreads();
    if (t == 0) {
        float s = 0.f;
#pragma unroll
        for (int i = 0; i < 8; i++) s += spart[i];
        atomicAdd(&g_diff, (double)s);
    }
}

__global__ void k_final(float* __restrict__ out) {
    out[ZQ_ELEMS] = (float)(0.25 * g_diff / (double)ZQ_ELEMS);
}

extern "C" void kernel_launch(void* const* d_in, const int* in_sizes, int n_in,
                              void* d_out, int out_size) {
    const float* z   = (const float*)d_in[0];
    const float* emb = (const float*)d_in[1];
    float* out = (float*)d_out;

    cudaFuncSetAttribute(k_gemm,
                         cudaFuncAttributeMaxDynamicSharedMemorySize,
                         SMEM_ALLOC);

    k_prep<<<N_EMB / 8, 256>>>(emb);
    dim3 g(NQ / QT, SPLITS);
    k_gemm<<<g, 256, SMEM_ALLOC>>>(z, emb);
    k_reduce<<<NQ / 256, 256>>>();
    k_refine<<<2048, 256>>>(z, emb);
    k_scatter<<<BB * (HW / 32), 256>>>(z, emb, out);
    k_final<<<1, 1>>>(out);
}

// round 8
// speedup vs baseline: 3.7583x; 1.1532x over previous
#include <cuda_runtime.h>
#include <cuda_fp16.h>
#include <cstdint>
#include <cfloat>

#define N_EMB   8192
#define DDIM    256
#define BB      32
#define HW      1024
#define NQ      32768
#define ZQ_ELEMS 8388608
#define SPLITS  4
#define KSPL    2048
#define QT      128
#define CCH     128
#define GCH     256
#define TAU     0.20f

#define SM_A    0               // 128 q x 256 k halves, swizzled = 65536 B
#define SM_B    65536           // 2 stages x 16384 B
#define SM_EH   98304           // 2048 floats
#define SM_RED  106496          // rv1/ri1/rv2 3 x 2048 B
#define SMEM_ALLOC 112640

__device__ float  g_ehn[N_EMB];
__device__ __half g_eh[N_EMB * DDIM];
__device__ float  g_p1v[SPLITS * NQ];
__device__ int    g_p1i[SPLITS * NQ];
__device__ float  g_p2v[SPLITS * NQ];
__device__ float  g_cmin[GCH * NQ];
__device__ float  g_b1[NQ];
__device__ int    g_idx[NQ];
__device__ int    g_flag[NQ];
__device__ int    g_nflag;
__device__ double g_diff;

__device__ __forceinline__ uint32_t smem_u32(const void* p) {
    uint32_t a;
    asm("{ .reg .u64 t; cvta.to.shared.u64 t, %1; cvt.u32.u64 %0, t; }"
        : "=r"(a) : "l"(p));
    return a;
}
__device__ __forceinline__ void cp16(uint32_t s, const void* g) {
    asm volatile("cp.async.cg.shared.global [%0], [%1], 16;"
                 :: "r"(s), "l"(g) : "memory");
}
#define CP_COMMIT() asm volatile("cp.async.commit_group;" ::: "memory")
#define CP_WAIT1()  asm volatile("cp.async.wait_group 1;" ::: "memory")

#define LDMX4(r0, r1, r2, r3, addr) \
    asm volatile("ldmatrix.sync.aligned.m8n8.x4.shared.b16 {%0,%1,%2,%3},[%4];" \
        : "=r"(r0), "=r"(r1), "=r"(r2), "=r"(r3) : "r"(addr))
#define LDMX2(r0, r1, addr) \
    asm volatile("ldmatrix.sync.aligned.m8n8.x2.shared.b16 {%0,%1},[%2];" \
        : "=r"(r0), "=r"(r1) : "r"(addr))
#define MMA_F16(d, a, b0, b1) \
    asm volatile("mma.sync.aligned.m16n8k16.row.col.f32.f16.f16.f32 " \
        "{%0,%1,%2,%3},{%4,%5,%6,%7},{%8,%9},{%0,%1,%2,%3};" \
        : "+f"((d)[0]), "+f"((d)[1]), "+f"((d)[2]), "+f"((d)[3]) \
        : "r"((a)[0]), "r"((a)[1]), "r"((a)[2]), "r"((a)[3]), "r"(b0), "r"(b1))

__global__ void k_prep(const float* __restrict__ emb) {
    if (blockIdx.x == 0 && threadIdx.x == 0) { g_diff = 0.0; g_nflag = 0; }
    int row  = blockIdx.x * 8 + (threadIdx.x >> 5);
    int lane = threadIdx.x & 31;
    const float4* e4 = (const float4*)(emb + (size_t)row * DDIM);
    __half2* eh2 = (__half2*)(g_eh + (size_t)row * DDIM);
    float s = 0.f;
    for (int i = lane; i < DDIM / 4; i += 32) {
        float4 v = e4[i];
        s += v.x * v.x + v.y * v.y + v.z * v.z + v.w * v.w;
        eh2[2 * i]     = __floats2half2_rn(v.x, v.y);
        eh2[2 * i + 1] = __floats2half2_rn(v.z, v.w);
    }
#pragma unroll
    for (int o = 16; o; o >>= 1) s += __shfl_xor_sync(0xffffffffu, s, o);
    if (lane == 0) g_ehn[row] = 0.5f * s;
}

// grid (NQ/QT=256, SPLITS=4), block 256 (8 warps: 2M x 4N), 2 CTAs/SM
__global__ void __launch_bounds__(256, 2)
k_gemm(const float* __restrict__ z) {
    extern __shared__ char sm[];
    const uint32_t smA = smem_u32(sm);
    float* ehs = (float*)(sm + SM_EH);
    float* rv1 = (float*)(sm + SM_RED);
    int*   ri1 = (int*)(sm + SM_RED + 2048);
    float* rv2 = (float*)(sm + SM_RED + 4096);

    const int tid = threadIdx.x, wid = tid >> 5, lane = tid & 31;
    const int warpM = wid >> 2, warpN = wid & 3;
    const int g = lane >> 2, t = lane & 3;
    const int qbase = blockIdx.x * QT, sp = blockIdx.y;
    const int bb = qbase / HW, nb = qbase % HW;
    const int kbase = sp * KSPL;

    for (int i = tid; i < KSPL; i += 256) ehs[i] = g_ehn[kbase + i];

    // A staging: z[128 q][256 k] -> half, swizzled [q][kblk^q]
    const float* zb = z + (size_t)bb * DDIM * HW + nb;
    for (int i = tid; i < QT * DDIM; i += 256) {
        int q = i & 127, k = i >> 7;
        __half hv = __float2half_rn(zb[(size_t)k * HW + q]);
        int kblk = k >> 3;
        uint32_t off = q * 512 + (((kblk & 24) | ((kblk ^ q) & 7)) << 4)
                     + (k & 7) * 2;
        *(__half*)(sm + off) = hv;
    }

    auto prefetch = [&](int s) {
        int cc = s >> 2, kb = s & 3, buf = s & 1;
        const __half* src = g_eh + (size_t)(kbase + cc * CCH) * DDIM + kb * 64;
        uint32_t dst = smA + 65536 + buf * 16384;
#pragma unroll
        for (int it = 0; it < 4; it++) {
            int idx = it * 256 + tid;
            int code = idx >> 3, kblk = idx & 7;
            cp16(dst + code * 128 + (((kblk ^ code) & 7) << 4),
                 src + (size_t)code * DDIM + kblk * 8);
        }
    };

    float D[4][4][4];
    float bv1[4][2], bv2[4][2];
    int   bix[4][2];
#pragma unroll
    for (int a = 0; a < 4; a++)
#pragma unroll
        for (int h = 0; h < 2; h++) {
            bv1[a][h] = FLT_MAX; bv2[a][h] = FLT_MAX; bix[a][h] = 0;
        }

    prefetch(0);
    CP_COMMIT();
    const int r_ld  = (lane & 7) | (lane & 8);        // A frag row 0..15
    const int cbhi  = (lane >> 4) & 1;                // A col halfblock
    const int crow8 = lane & 7;                       // B frag code row
    const int kbhi  = (lane >> 3) & 1;                // B k halfblock

    for (int s = 0; s < 64; s++) {
        if (s < 63) prefetch(s + 1);
        CP_COMMIT();
        CP_WAIT1();
        __syncthreads();
        if ((s & 3) == 0) {
#pragma unroll
            for (int mt = 0; mt < 4; mt++)
#pragma unroll
                for (int nt = 0; nt < 4; nt++)
#pragma unroll
                    for (int c = 0; c < 4; c++) D[mt][nt][c] = 0.f;
        }
        const uint32_t bst = smA + 65536 + (s & 1) * 16384;
#pragma unroll
        for (int ks = 0; ks < 4; ks++) {
            const int kk = (s & 3) * 4 + ks;
            const int cb = kk * 2 + cbhi;
            uint32_t a[4][4];
#pragma unroll
            for (int mt = 0; mt < 4; mt++) {
                int mrow = warpM * 64 + mt * 16 + r_ld;
                uint32_t ad = smA + mrow * 512
                            + (((cb & 24) | ((cb ^ mrow) & 7)) << 4);
                LDMX4(a[mt][0], a[mt][1], a[mt][2], a[mt][3], ad);
            }
            const int kb2 = ks * 2 + kbhi;
#pragma unroll
            for (int nt = 0; nt < 4; nt++) {
                int crow = warpN * 32 + nt * 8 + crow8;
                uint32_t bad = bst + crow * 128 + (((kb2 ^ crow) & 7) << 4);
                uint32_t b0, b1;
                LDMX2(b0, b1, bad);
#pragma unroll
                for (int mt = 0; mt < 4; mt++)
                    MMA_F16(D[mt][nt], a[mt], b0, b1);
            }
        }
        if ((s & 3) == 3) {
            const int cc = s >> 2;
            float eh[4][2];
#pragma unroll
            for (int nt = 0; nt < 4; nt++) {
                int cl = cc * CCH + warpN * 32 + nt * 8 + 2 * t;
                eh[nt][0] = ehs[cl]; eh[nt][1] = ehs[cl + 1];
            }
#pragma unroll
            for (int mt = 0; mt < 4; mt++)
#pragma unroll
                for (int h = 0; h < 2; h++) {
                    float cm = FLT_MAX;
#pragma unroll
                    for (int nt = 0; nt < 4; nt++)
#pragma unroll
                        for (int c = 0; c < 2; c++) {
                            float v = eh[nt][c] - D[mt][nt][h * 2 + c];
                            int gi = kbase + cc * CCH + warpN * 32 + nt * 8
                                   + 2 * t + c;
                            cm = fminf(cm, v);
                            if (v < bv1[mt][h] ||
                                (v == bv1[mt][h] && gi < bix[mt][h])) {
                                bv2[mt][h] = bv1[mt][h];
                                bv1[mt][h] = v; bix[mt][h] = gi;
                            } else {
                                bv2[mt][h] = fminf(bv2[mt][h], v);
                            }
                        }
                    cm = fminf(cm, __shfl_xor_sync(0xffffffffu, cm, 1));
                    cm = fminf(cm, __shfl_xor_sync(0xffffffffu, cm, 2));
                    if (t == 0) {
                        int slice = sp * 64 + cc * 4 + warpN;
                        int row = warpM * 64 + mt * 16 + h * 8 + g;
                        g_cmin[(size_t)slice * NQ + qbase + row] = cm;
                    }
                }
        }
        __syncthreads();
    }

#pragma unroll
    for (int mt = 0; mt < 4; mt++)
#pragma unroll
        for (int h = 0; h < 2; h++) {
            float v1 = bv1[mt][h], v2 = bv2[mt][h];
            int i1 = bix[mt][h];
#pragma unroll
            for (int o = 1; o <= 2; o <<= 1) {
                float pv1 = __shfl_xor_sync(0xffffffffu, v1, o);
                float pv2 = __shfl_xor_sync(0xffffffffu, v2, o);
                int   pi1 = __shfl_xor_sync(0xffffffffu, i1, o);
                if (pv1 < v1 || (pv1 == v1 && pi1 < i1)) {
                    v2 = fminf(v1, pv2); v1 = pv1; i1 = pi1;
                } else {
                    v2 = fminf(pv1, v2);
                }
            }
            if (t == 0) {
                int row = warpM * 64 + mt * 16 + h * 8 + g;
                rv1[row * 4 + warpN] = v1;
                ri1[row * 4 + warpN] = i1;
                rv2[row * 4 + warpN] = v2;
            }
        }
    __syncthreads();
    if (tid < 128) {
        float v1 = rv1[tid * 4]; int i1 = ri1[tid * 4]; float v2 = rv2[tid * 4];
#pragma unroll
        for (int wn = 1; wn < 4; wn++) {
            float pv1 = rv1[tid * 4 + wn], pv2 = rv2[tid * 4 + wn];
            int   pi1 = ri1[tid * 4 + wn];
            if (pv1 < v1 || (pv1 == v1 && pi1 < i1)) {
                v2 = fminf(v1, pv2); v1 = pv1; i1 = pi1;
            } else {
                v2 = fminf(pv1, v2);
            }
        }
        g_p1v[sp * NQ + qbase + tid] = v1;
        g_p1i[sp * NQ + qbase + tid] = i1;
        g_p2v[sp * NQ + qbase + tid] = v2;
    }
}

__global__ void k_reduce() {
    int q = blockIdx.x * 256 + threadIdx.x;
    float b1 = FLT_MAX, b2 = FLT_MAX;
    int i1 = 0;
#pragma unroll
    for (int s = 0; s < SPLITS; s++) {
        float v1 = g_p1v[s * NQ + q];
        int   ii = g_p1i[s * NQ + q];
        float v2 = g_p2v[s * NQ + q];
        if (v1 < b1) { b2 = b1; b1 = v1; i1 = ii; }
        else if (v1 < b2) b2 = v1;
        if (v2 < b2) b2 = v2;
    }
    g_idx[q] = i1;
    g_b1[q]  = b1;
    if (b2 - b1 <= TAU) {
        int p = atomicAdd(&g_nflag, 1);
        g_flag[p] = q;
    }
}

__global__ void __launch_bounds__(256, 2)
k_refine(const float* __restrict__ z, const float* __restrict__ emb) {
    __shared__ float zs[DDIM];
    __shared__ short clist[GCH];
    __shared__ int   ncand;
    __shared__ float wv[8];
    __shared__ int   wi[8];
    const int tid = threadIdx.x, wid = tid >> 5, lane = tid & 31;
    const int grp = lane >> 3, gl = lane & 7;
    const int nf = g_nflag;
    for (int fi = blockIdx.x; fi < nf; fi += gridDim.x) {
        const int q = g_flag[fi];
        if (tid == 0) ncand = 0;
        __syncthreads();
        zs[tid] = z[((size_t)(q >> 10) * DDIM + tid) * HW + (q & (HW - 1))];
        __syncthreads();
        float4 zr[8];
#pragma unroll
        for (int j = 0; j < 8; j++) zr[j] = *(const float4*)(zs + gl * 32 + j * 4);
        const float thr = g_b1[q] + TAU;
        if (tid < GCH && g_cmin[(size_t)tid * NQ + q] <= thr) {
            int p = atomicAdd(&ncand, 1);
            clist[p] = (short)tid;
        }
        __syncthreads();
        const int nc = ncand;
        float bv = FLT_MAX;
        int   bi = 0x7fffffff;
        for (int ci = 0; ci < nc; ci++) {
            const int code = clist[ci] * 32 + wid * 4 + grp;
            const float4* er = (const float4*)(emb + (size_t)code * DDIM + gl * 32);
            float s = 0.f;
#pragma unroll
            for (int j = 0; j < 8; j++) {
                float4 e = er[j];
                s += e.x * zr[j].x + e.y * zr[j].y + e.z * zr[j].z + e.w * zr[j].w;
            }
            s += __shfl_xor_sync(0xffffffffu, s, 1);
            s += __shfl_xor_sync(0xffffffffu, s, 2);
            s += __shfl_xor_sync(0xffffffffu, s, 4);
            float v = g_ehn[code] - s;
            if (v < bv || (v == bv && code < bi)) { bv = v; bi = code; }
        }
#pragma unroll
        for (int o = 8; o <= 16; o <<= 1) {
            float pv = __shfl_xor_sync(0xffffffffu, bv, o);
            int   pi = __shfl_xor_sync(0xffffffffu, bi, o);
            if (pv < bv || (pv == bv && pi < bi)) { bv = pv; bi = pi; }
        }
        if (lane == 0) { wv[wid] = bv; wi[wid] = bi; }
        __syncthreads();
        if (tid == 0) {
            float fv = wv[0]; int fx = wi[0];
#pragma unroll
            for (int w2 = 1; w2 < 8; w2++)
                if (wv[w2] < fv || (wv[w2] == fv && wi[w2] < fx)) {
                    fv = wv[w2]; fx = wi[w2];
                }
            g_idx[q] = fx;
        }
        __syncthreads();
    }
}

__global__ void k_scatter(const float* __restrict__ z,
                          const float* __restrict__ emb,
                          float* __restrict__ out) {
    __shared__ float Ts[32][257];
    __shared__ int   sidx[32];
    __shared__ float spart[8];
    const int bh = blockIdx.x;
    const int b  = bh >> 5;
    const int h  = bh & 31;
    const int t  = threadIdx.x;

    if (t < 32) {
        int ix = g_idx[b * HW + h * 32 + t];
        sidx[t] = ix;
        out[ZQ_ELEMS + 1 + b * HW + h * 32 + t] = (float)ix;
    }
    __syncthreads();
    {
        const int wr = t >> 3;
        const int c0 = (t & 7) * 32;
        const float* er = emb + (size_t)sidx[wr] * DDIM + c0;
        for (int c = 0; c < 32; c += 4) {
            float4 v = *(const float4*)(er + c);
            Ts[wr][c0 + c + 0] = v.x;
            Ts[wr][c0 + c + 1] = v.y;
            Ts[wr][c0 + c + 2] = v.z;
            Ts[wr][c0 + c + 3] = v.w;
        }
    }
    __syncthreads();

    float ds = 0.f;
    const int w  = t & 31;
    const int cg = t >> 5;
    const size_t basebh = (size_t)b * DDIM * HW + (size_t)h * 32;
    for (int c = cg; c < DDIM; c += 8) {
        float v = Ts[w][c];
        size_t gg = basebh + (size_t)c * HW + w;
        float zv = z[gg];
        out[gg] = v;
        float df = v - zv;
        ds += df * df;
    }
#pragma unroll
    for (int o = 16; o; o >>= 1) ds += __shfl_xor_sync(0xffffffffu, ds, o);
    if ((t & 31) == 0) spart[t >> 5] = ds;
    __syncthreads();
    if (t == 0) {
        float s = 0.f;
#pragma unroll
        for (int i = 0; i < 8; i++) s += spart[i];
        atomicAdd(&g_diff, (double)s);
    }
}

__global__ void k_final(float* __restrict__ out) {
    out[ZQ_ELEMS] = (float)(0.25 * g_diff / (double)ZQ_ELEMS);
}

extern "C" void kernel_launch(void* const* d_in, const int* in_sizes, int n_in,
                              void* d_out, int out_size) {
    const float* z   = (const float*)d_in[0];
    const float* emb = (const float*)d_in[1];
    float* out = (float*)d_out;

    cudaFuncSetAttribute(k_gemm,
                         cudaFuncAttributeMaxDynamicSharedMemorySize,
                         SMEM_ALLOC);

    k_prep<<<N_EMB / 8, 256>>>(emb);
    dim3 g(NQ / QT, SPLITS);
    k_gemm<<<g, 256, SMEM_ALLOC>>>(z);
    k_reduce<<<NQ / 256, 256>>>();
    k_refine<<<2048, 256>>>(z, emb);
    k_scatter<<<BB * (HW / 32), 256>>>(z, emb, out);
    k_final<<<1, 1>>>(out);
}

// round 9
// speedup vs baseline: 5.6435x; 1.5016x over previous
#include <cuda_runtime.h>
#include <cuda_fp16.h>
#include <cstdint>
#include <cfloat>

#define N_EMB   8192
#define DDIM    256
#define BB      32
#define HW      1024
#define NQ      32768
#define ZQ_ELEMS 8388608
#define SPLITS  8
#define KSPL    1024
#define QT      128
#define CCH     128
#define GCH     256
#define NST     32
#define TAU     0.20f

#define SM_A    0               // 128 q x 256 k halves, swizzled = 65536 B
#define SM_B    65536           // 2 stages x 16384 B
#define SM_EH   98304           // 1024 floats
#define SM_RED  106496          // rv1/ri1/rv2 3 x 2048 B
#define SMEM_ALLOC 112640

__device__ float  g_ehn[N_EMB];
__device__ __half g_eh[N_EMB * DDIM];
__device__ float  g_p1v[SPLITS * NQ];
__device__ int    g_p1i[SPLITS * NQ];
__device__ float  g_p2v[SPLITS * NQ];
__device__ float  g_cmin[GCH * NQ];
__device__ float  g_b1[NQ];
__device__ int    g_idx[NQ];
__device__ int    g_flag[NQ];
__device__ int    g_nflag;
__device__ double g_diff;

__device__ __forceinline__ uint32_t smem_u32(const void* p) {
    uint32_t a;
    asm("{ .reg .u64 t; cvta.to.shared.u64 t, %1; cvt.u32.u64 %0, t; }"
        : "=r"(a) : "l"(p));
    return a;
}
__device__ __forceinline__ void cp16(uint32_t s, const void* g) {
    asm volatile("cp.async.cg.shared.global [%0], [%1], 16;"
                 :: "r"(s), "l"(g) : "memory");
}
#define CP_COMMIT() asm volatile("cp.async.commit_group;" ::: "memory")
#define CP_WAIT0()  asm volatile("cp.async.wait_group 0;" ::: "memory")

#define LDMX4(r0, r1, r2, r3, addr) \
    asm volatile("ldmatrix.sync.aligned.m8n8.x4.shared.b16 {%0,%1,%2,%3},[%4];" \
        : "=r"(r0), "=r"(r1), "=r"(r2), "=r"(r3) : "r"(addr))
#define LDMX2(r0, r1, addr) \
    asm volatile("ldmatrix.sync.aligned.m8n8.x2.shared.b16 {%0,%1},[%2];" \
        : "=r"(r0), "=r"(r1) : "r"(addr))
#define MMA_F16(d, a, b0, b1) \
    asm volatile("mma.sync.aligned.m16n8k16.row.col.f32.f16.f16.f32 " \
        "{%0,%1,%2,%3},{%4,%5,%6,%7},{%8,%9},{%0,%1,%2,%3};" \
        : "+f"((d)[0]), "+f"((d)[1]), "+f"((d)[2]), "+f"((d)[3]) \
        : "r"((a)[0]), "r"((a)[1]), "r"((a)[2]), "r"((a)[3]), "r"(b0), "r"(b1))

__global__ void k_prep(const float* __restrict__ emb) {
    if (blockIdx.x == 0 && threadIdx.x == 0) { g_diff = 0.0; g_nflag = 0; }
    int row  = blockIdx.x * 8 + (threadIdx.x >> 5);
    int lane = threadIdx.x & 31;
    const float4* e4 = (const float4*)(emb + (size_t)row * DDIM);
    __half2* eh2 = (__half2*)(g_eh + (size_t)row * DDIM);
    float s = 0.f;
    for (int i = lane; i < DDIM / 4; i += 32) {
        float4 v = e4[i];
        s += v.x * v.x + v.y * v.y + v.z * v.z + v.w * v.w;
        eh2[2 * i]     = __floats2half2_rn(v.x, v.y);
        eh2[2 * i + 1] = __floats2half2_rn(v.z, v.w);
    }
#pragma unroll
    for (int o = 16; o; o >>= 1) s += __shfl_xor_sync(0xffffffffu, s, o);
    if (lane == 0) g_ehn[row] = 0.5f * s;
}

// grid (NQ/QT=256, SPLITS=8), block 256 (8 warps: 2M x 4N), 2 CTAs/SM
__global__ void __launch_bounds__(256, 2)
k_gemm(const float* __restrict__ z) {
    extern __shared__ char sm[];
    const uint32_t smA = smem_u32(sm);
    float* ehs = (float*)(sm + SM_EH);
    float* rv1 = (float*)(sm + SM_RED);
    int*   ri1 = (int*)(sm + SM_RED + 2048);
    float* rv2 = (float*)(sm + SM_RED + 4096);

    const int tid = threadIdx.x, wid = tid >> 5, lane = tid & 31;
    const int warpM = wid >> 2, warpN = wid & 3;
    const int g = lane >> 2, t = lane & 3;
    const int qbase = blockIdx.x * QT, sp = blockIdx.y;
    const int bb = qbase / HW, nb = qbase % HW;
    const int kbase = sp * KSPL;

    for (int i = tid; i < KSPL; i += 256) ehs[i] = g_ehn[kbase + i];

    // A staging: z[128 q][256 k] -> half, swizzled [q][kblk^q]
    const float* zb = z + (size_t)bb * DDIM * HW + nb;
    for (int i = tid; i < QT * DDIM; i += 256) {
        int q = i & 127, k = i >> 7;
        __half hv = __float2half_rn(zb[(size_t)k * HW + q]);
        int kblk = k >> 3;
        uint32_t off = q * 512 + (((kblk & 24) | ((kblk ^ q) & 7)) << 4)
                     + (k & 7) * 2;
        *(__half*)(sm + off) = hv;
    }

    auto prefetch = [&](int s) {
        int cc = s >> 2, kb = s & 3, buf = s & 1;
        const __half* src = g_eh + (size_t)(kbase + cc * CCH) * DDIM + kb * 64;
        uint32_t dst = smA + 65536 + buf * 16384;
#pragma unroll
        for (int it = 0; it < 4; it++) {
            int idx = it * 256 + tid;
            int code = idx >> 3, kblk = idx & 7;
            cp16(dst + code * 128 + (((kblk ^ code) & 7) << 4),
                 src + (size_t)code * DDIM + kblk * 8);
        }
    };

    float D[4][4][4];
    float bv1[4][2], bv2[4][2];
    int   bix[4][2];
#pragma unroll
    for (int a = 0; a < 4; a++)
#pragma unroll
        for (int h = 0; h < 2; h++) {
            bv1[a][h] = FLT_MAX; bv2[a][h] = FLT_MAX; bix[a][h] = 0;
        }

    prefetch(0);
    CP_COMMIT();
    const int r_ld  = (lane & 7) | (lane & 8);        // A frag row 0..15
    const int cbhi  = (lane >> 4) & 1;                // A col halfblock
    const int crow8 = lane & 7;                       // B frag code row
    const int kbhi  = (lane >> 3) & 1;                // B k halfblock

    for (int s = 0; s < NST; s++) {
        CP_WAIT0();
        __syncthreads();          // buf s ready AND all warps done with s-1
        if (s + 1 < NST) { prefetch(s + 1); CP_COMMIT(); }
        if ((s & 3) == 0) {
#pragma unroll
            for (int mt = 0; mt < 4; mt++)
#pragma unroll
                for (int nt = 0; nt < 4; nt++)
#pragma unroll
                    for (int c = 0; c < 4; c++) D[mt][nt][c] = 0.f;
        }
        const uint32_t bst = smA + 65536 + (s & 1) * 16384;
#pragma unroll
        for (int ks = 0; ks < 4; ks++) {
            const int kk = (s & 3) * 4 + ks;
            const int cb = kk * 2 + cbhi;
            uint32_t a[4][4];
#pragma unroll
            for (int mt = 0; mt < 4; mt++) {
                int mrow = warpM * 64 + mt * 16 + r_ld;
                uint32_t ad = smA + mrow * 512
                            + (((cb & 24) | ((cb ^ mrow) & 7)) << 4);
                LDMX4(a[mt][0], a[mt][1], a[mt][2], a[mt][3], ad);
            }
            const int kb2 = ks * 2 + kbhi;
#pragma unroll
            for (int nt = 0; nt < 4; nt++) {
                int crow = warpN * 32 + nt * 8 + crow8;
                uint32_t bad = bst + crow * 128 + (((kb2 ^ crow) & 7) << 4);
                uint32_t b0, b1;
                LDMX2(b0, b1, bad);
#pragma unroll
                for (int mt = 0; mt < 4; mt++)
                    MMA_F16(D[mt][nt], a[mt], b0, b1);
            }
        }
        if ((s & 3) == 3) {
            const int cc = s >> 2;
            float eh[4][2];
#pragma unroll
            for (int nt = 0; nt < 4; nt++) {
                int cl = cc * CCH + warpN * 32 + nt * 8 + 2 * t;
                eh[nt][0] = ehs[cl]; eh[nt][1] = ehs[cl + 1];
            }
#pragma unroll
            for (int mt = 0; mt < 4; mt++)
#pragma unroll
                for (int h = 0; h < 2; h++) {
                    float cm = FLT_MAX;
#pragma unroll
                    for (int nt = 0; nt < 4; nt++)
#pragma unroll
                        for (int c = 0; c < 2; c++) {
                            float v = eh[nt][c] - D[mt][nt][h * 2 + c];
                            int gi = kbase + cc * CCH + warpN * 32 + nt * 8
                                   + 2 * t + c;
                            cm = fminf(cm, v);
                            if (v < bv1[mt][h] ||
                                (v == bv1[mt][h] && gi < bix[mt][h])) {
                                bv2[mt][h] = bv1[mt][h];
                                bv1[mt][h] = v; bix[mt][h] = gi;
                            } else {
                                bv2[mt][h] = fminf(bv2[mt][h], v);
                            }
                        }
                    cm = fminf(cm, __shfl_xor_sync(0xffffffffu, cm, 1));
                    cm = fminf(cm, __shfl_xor_sync(0xffffffffu, cm, 2));
                    if (t == 0) {
                        int slice = sp * 32 + cc * 4 + warpN;
                        int row = warpM * 64 + mt * 16 + h * 8 + g;
                        g_cmin[(size_t)slice * NQ + qbase + row] = cm;
                    }
                }
        }
    }
    __syncthreads();

#pragma unroll
    for (int mt = 0; mt < 4; mt++)
#pragma unroll
        for (int h = 0; h < 2; h++) {
            float v1 = bv1[mt][h], v2 = bv2[mt][h];
            int i1 = bix[mt][h];
#pragma unroll
            for (int o = 1; o <= 2; o <<= 1) {
                float pv1 = __shfl_xor_sync(0xffffffffu, v1, o);
                float pv2 = __shfl_xor_sync(0xffffffffu, v2, o);
                int   pi1 = __shfl_xor_sync(0xffffffffu, i1, o);
                if (pv1 < v1 || (pv1 == v1 && pi1 < i1)) {
                    v2 = fminf(v1, pv2); v1 = pv1; i1 = pi1;
                } else {
                    v2 = fminf(pv1, v2);
                }
            }
            if (t == 0) {
                int row = warpM * 64 + mt * 16 + h * 8 + g;
                rv1[row * 4 + warpN] = v1;
                ri1[row * 4 + warpN] = i1;
                rv2[row * 4 + warpN] = v2;
            }
        }
    __syncthreads();
    if (tid < 128) {
        float v1 = rv1[tid * 4]; int i1 = ri1[tid * 4]; float v2 = rv2[tid * 4];
#pragma unroll
        for (int wn = 1; wn < 4; wn++) {
            float pv1 = rv1[tid * 4 + wn], pv2 = rv2[tid * 4 + wn];
            int   pi1 = ri1[tid * 4 + wn];
            if (pv1 < v1 || (pv1 == v1 && pi1 < i1)) {
                v2 = fminf(v1, pv2); v1 = pv1; i1 = pi1;
            } else {
                v2 = fminf(pv1, v2);
            }
        }
        g_p1v[sp * NQ + qbase + tid] = v1;
        g_p1i[sp * NQ + qbase + tid] = i1;
        g_p2v[sp * NQ + qbase + tid] = v2;
    }
}

__global__ void k_reduce() {
    int q = blockIdx.x * 256 + threadIdx.x;
    float b1 = FLT_MAX, b2 = FLT_MAX;
    int i1 = 0;
#pragma unroll
    for (int s = 0; s < SPLITS; s++) {
        float v1 = g_p1v[s * NQ + q];
        int   ii = g_p1i[s * NQ + q];
        float v2 = g_p2v[s * NQ + q];
        if (v1 < b1) { b2 = b1; b1 = v1; i1 = ii; }
        else if (v1 < b2) b2 = v1;
        if (v2 < b2) b2 = v2;
    }
    g_idx[q] = i1;
    g_b1[q]  = b1;
    if (b2 - b1 <= TAU) {
        int p = atomicAdd(&g_nflag, 1);
        g_flag[p] = q;
    }
}

__global__ void __launch_bounds__(256, 2)
k_refine(const float* __restrict__ z, const float* __restrict__ emb) {
    __shared__ float zs[DDIM];
    __shared__ short clist[GCH];
    __shared__ int   ncand;
    __shared__ float wv[8];
    __shared__ int   wi[8];
    const int tid = threadIdx.x, wid = tid >> 5, lane = tid & 31;
    const int grp = lane >> 3, gl = lane & 7;
    const int nf = g_nflag;
    for (int fi = blockIdx.x; fi < nf; fi += gridDim.x) {
        const int q = g_flag[fi];
        if (tid == 0) ncand = 0;
        __syncthreads();
        zs[tid] = z[((size_t)(q >> 10) * DDIM + tid) * HW + (q & (HW - 1))];
        __syncthreads();
        float4 zr[8];
#pragma unroll
        for (int j = 0; j < 8; j++) zr[j] = *(const float4*)(zs + gl * 32 + j * 4);
        const float thr = g_b1[q] + TAU;
        if (tid < GCH && g_cmin[(size_t)tid * NQ + q] <= thr) {
            int p = atomicAdd(&ncand, 1);
            clist[p] = (short)tid;
        }
        __syncthreads();
        const int nc = ncand;
        float bv = FLT_MAX;
        int   bi = 0x7fffffff;
        for (int ci = 0; ci < nc; ci++) {
            const int code = clist[ci] * 32 + wid * 4 + grp;
            const float4* er = (const float4*)(emb + (size_t)code * DDIM + gl * 32);
            float s = 0.f;
#pragma unroll
            for (int j = 0; j < 8; j++) {
                float4 e = er[j];
                s += e.x * zr[j].x + e.y * zr[j].y + e.z * zr[j].z + e.w * zr[j].w;
            }
            s += __shfl_xor_sync(0xffffffffu, s, 1);
            s += __shfl_xor_sync(0xffffffffu, s, 2);
            s += __shfl_xor_sync(0xffffffffu, s, 4);
            float v = g_ehn[code] - s;
            if (v < bv || (v == bv && code < bi)) { bv = v; bi = code; }
        }
#pragma unroll
        for (int o = 8; o <= 16; o <<= 1) {
            float pv = __shfl_xor_sync(0xffffffffu, bv, o);
            int   pi = __shfl_xor_sync(0xffffffffu, bi, o);
            if (pv < bv || (pv == bv && pi < bi)) { bv = pv; bi = pi; }
        }
        if (lane == 0) { wv[wid] = bv; wi[wid] = bi; }
        __syncthreads();
        if (tid == 0) {
            float fv = wv[0]; int fx = wi[0];
#pragma unroll
            for (int w2 = 1; w2 < 8; w2++)
                if (wv[w2] < fv || (wv[w2] == fv && wi[w2] < fx)) {
                    fv = wv[w2]; fx = wi[w2];
                }
            g_idx[q] = fx;
        }
        __syncthreads();
    }
}

__global__ void k_scatter(const float* __restrict__ z,
                          const float* __restrict__ emb,
                          float* __restrict__ out) {
    __shared__ float Ts[32][257];
    __shared__ int   sidx[32];
    __shared__ float spart[8];
    const int bh = blockIdx.x;
    const int b  = bh >> 5;
    const int h  = bh & 31;
    const int t  = threadIdx.x;

    if (t < 32) {
        int ix = g_idx[b * HW + h * 32 + t];
        sidx[t] = ix;
        out[ZQ_ELEMS + 1 + b * HW + h * 32 + t] = (float)ix;
    }
    __syncthreads();
    {
        const int wr = t >> 3;
        const int c0 = (t & 7) * 32;
        const float* er = emb + (size_t)sidx[wr] * DDIM + c0;
        for (int c = 0; c < 32; c += 4) {
            float4 v = *(const float4*)(er + c);
            Ts[wr][c0 + c + 0] = v.x;
            Ts[wr][c0 + c + 1] = v.y;
            Ts[wr][c0 + c + 2] = v.z;
            Ts[wr][c0 + c + 3] = v.w;
        }
    }
    __syncthreads();

    float ds = 0.f;
    const int w  = t & 31;
    const int cg = t >> 5;
    const size_t basebh = (size_t)b * DDIM * HW + (size_t)h * 32;
    for (int c = cg; c < DDIM; c += 8) {
        float v = Ts[w][c];
        size_t gg = basebh + (size_t)c * HW + w;
        float zv = z[gg];
        out[gg] = v;
        float df = v - zv;
        ds += df * df;
    }
#pragma unroll
    for (int o = 16; o; o >>= 1) ds += __shfl_xor_sync(0xffffffffu, ds, o);
    if ((t & 31) == 0) spart[t >> 5] = ds;
    __syncthreads();
    if (t == 0) {
        float s = 0.f;
#pragma unroll
        for (int i = 0; i < 8; i++) s += spart[i];
        atomicAdd(&g_diff, (double)s);
    }
}

__global__ void k_final(float* __restrict__ out) {
    out[ZQ_ELEMS] = (float)(0.25 * g_diff / (double)ZQ_ELEMS);
}

extern "C" void kernel_launch(void* const* d_in, const int* in_sizes, int n_in,
                              void* d_out, int out_size) {
    const float* z   = (const float*)d_in[0];
    const float* emb = (const float*)d_in[1];
    float* out = (float*)d_out;

    cudaFuncSetAttribute(k_gemm,
                         cudaFuncAttributeMaxDynamicSharedMemorySize,
                         SMEM_ALLOC);

    k_prep<<<N_EMB / 8, 256>>>(emb);
    dim3 g(NQ / QT, SPLITS);
    k_gemm<<<g, 256, SMEM_ALLOC>>>(z);
    k_reduce<<<NQ / 256, 256>>>();
    k_refine<<<2048, 256>>>(z, emb);
    k_scatter<<<BB * (HW / 32), 256>>>(z, emb, out);
    k_final<<<1, 1>>>(out);
}